// round 16
// baseline (speedup 1.0000x reference)
#include <cuda_runtime.h>
#include <cuda_fp16.h>

#define NNODES 50000
#define NEDGES 800000
#define FIN0   128
#define F1     204      // 64+68+72
#define F2     260      // 132+128
#define LD1    208      // padded halves stride (16B-aligned rows)
#define SCAN_NB  49

// ---------------- device scratch ----------------
__device__ __align__(16) __half g_Hh[2][(size_t)NNODES * LD1];    // H1 (stride LD1), later Z2h (stride LD1)
__device__ __align__(16) __half g_lowh[2][(size_t)NNODES * LD1];  // fp16 low_result
__device__ __align__(16) __half g_xh[2][(size_t)NNODES * FIN0];   // fp16 copies of x,y (GEMM1 A)
__device__ __align__(16) __half g_fivh[2][(size_t)NNODES * 128];  // fp16 h_fiv (GEMM3 A)
__device__ __align__(16) float  g_fou[2][(size_t)NNODES * 132];
__device__ __align__(16) __half g_Wc1T[F1 * FIN0];                // transposed fp16 weights [n][k]
__device__ __align__(16) __half g_Wc2T[F2 * F1];
__device__ __align__(16) __half g_WmT[132 * 128];
__device__ __align__(16) float  g_bc1[256];   // padded, pad stays zero
__device__ __align__(16) float  g_bc2[F2];
__device__ int    g_rowptr[2][NNODES + 2];
__device__ int    g_cnt[2][NNODES];   // always zero between runs: fill's atomicSub restores it
__device__ int    g_boff[2][64];
__device__ __align__(8) uint2  g_edge[2][NEDGES];  // {col, valbits}

__device__ __forceinline__ unsigned pack_h2(float a, float b) {
    __half2 h = __floats2half2_rn(a, b);
    return *(unsigned*)&h;
}

// ---------------- pack weights + convert x/y to fp16 (no hist) ----------------
__global__ void __launch_bounds__(256) pack_conv_kernel(
    const float* __restrict__ W1, const float* __restrict__ b1,
    const float* __restrict__ W2, const float* __restrict__ b2,
    const float* __restrict__ W3, const float* __restrict__ b3,
    const float* __restrict__ W4, const float* __restrict__ b4,
    const float* __restrict__ W5, const float* __restrict__ b5,
    const float* __restrict__ Wm,
    const float* __restrict__ x, const float* __restrict__ y)
{
    const int t = threadIdx.x;
    const int i = blockIdx.x * 256 + t;
    if (i < F1 * FIN0) {                 // Wc1T[n][k]
        int n = i / FIN0, k = i % FIN0;
        float v = (n < 64) ? W1[k * 64 + n]
                : (n < 132) ? W2[k * 68 + (n - 64)]
                            : W3[k * 72 + (n - 132)];
        g_Wc1T[i] = __float2half(v);
    }
    if (i < F2 * F1) {                   // Wc2T[n][k]
        int n = i / F1, k = i % F1;
        float v = (n < 132) ? W4[k * 132 + n] : W5[k * 128 + (n - 132)];
        g_Wc2T[i] = __float2half(v);
    }
    if (i < 132 * 128) {                 // WmT[n][k]
        int n = i / 128, k = i % 128;
        g_WmT[i] = __float2half(Wm[k * 132 + n]);
    }
    if (i < F1) g_bc1[i] = (i < 64) ? b1[i] : (i < 132) ? b2[i - 64] : b3[i - 132];
    if (i < F2) g_bc2[i] = (i < 132) ? b4[i] : b5[i - 132];
    // convert x,y -> fp16 (vectorized float2 -> half2), strided across full grid
    const int stride = gridDim.x * 256;
    const int nU = NNODES * FIN0 / 2;    // 3.2M uints per branch
    unsigned* dx = (unsigned*)g_xh[0];
    unsigned* dy = (unsigned*)g_xh[1];
    const float2* sx = (const float2*)x;
    const float2* sy = (const float2*)y;
    for (int idx = i; idx < nU; idx += stride) {
        float2 f = sx[idx]; dx[idx] = pack_h2(f.x, f.y);
        float2 g = sy[idx]; dy[idx] = pack_h2(g.x, g.y);
    }
}

// ---------------- per-branch histogram (block 0 zeroes boff, ordered before scan in-stream) ----------------
__global__ void __launch_bounds__(256) hist_kernel(int br, const int* __restrict__ idx) {
    if (blockIdx.x == 0 && threadIdx.x < 64) g_boff[br][threadIdx.x] = 0;
    int* cnt = g_cnt[br];
    const int stride = gridDim.x * 256;
    for (int e = blockIdx.x * 256 + threadIdx.x; e < NEDGES; e += stride)
        atomicAdd(&cnt[idx[e]], 1);
}

// ---------------- scan (per branch) ----------------
__global__ void __launch_bounds__(1024) scan1_kernel(int br) {
    __shared__ int warp_sums[32];
    __shared__ int sTot;
    const int b = blockIdx.x, t = threadIdx.x;
    const int i = b * 1024 + t;
    const int lane = t & 31, wid = t >> 5;
    int v = (i < NNODES) ? g_cnt[br][i] : 0;
    int s = v;
#pragma unroll
    for (int o = 1; o < 32; o <<= 1) {
        int u = __shfl_up_sync(0xFFFFFFFFu, s, o);
        if (lane >= o) s += u;
    }
    if (lane == 31) warp_sums[wid] = s;
    __syncthreads();
    if (wid == 0) {
        int ws = warp_sums[lane];
#pragma unroll
        for (int o = 1; o < 32; o <<= 1) {
            int u = __shfl_up_sync(0xFFFFFFFFu, ws, o);
            if (lane >= o) ws += u;
        }
        warp_sums[lane] = ws;
    }
    __syncthreads();
    int excl = s - v + (wid > 0 ? warp_sums[wid - 1] : 0);
    if (i <= NNODES) g_rowptr[br][i] = excl;
    if (t == 1023) sTot = excl + v;
    __syncthreads();
    int total = sTot;
    if (t > b && t < SCAN_NB) atomicAdd(&g_boff[br][t], total);
}

// ---------------- GEMM helpers ----------------
#define GBM 128
#define GBN 64
#define GBK 32
#define STA_LD 68   // staging row stride in floats: 272 B -> float4-aligned rows

__device__ __forceinline__ float4 add4(float4 a, float4 b) {
    return make_float4(a.x + b.x, a.y + b.y, a.z + b.z, a.w + b.w);
}
__device__ __forceinline__ float4 mul4(float4 a, float s) {
    return make_float4(s * a.x, s * a.y, s * a.z, s * a.w);
}
__device__ __forceinline__ void fma4h(float4& a, float v, uint2 h) {
    float2 lo = __half22float2(*(const __half2*)&h.x);
    float2 hi = __half22float2(*(const __half2*)&h.y);
    a.x += v * lo.x; a.y += v * lo.y; a.z += v * hi.x; a.w += v * hi.y;
}
__device__ __forceinline__ float sum4(float4 a) { return a.x + a.y + a.z + a.w; }

// ---------------- GEMM body (fp16 A, smem-staged coalesced epilogue) ----------------
// EPI: 0 = fp16 out (gemm1), 2 = split fou/fiv/fivh + bias (gemm2'), 3 = leaky + mlp + fin fuse (gemm3)
template<int EPI>
__device__ __forceinline__ void gemm_body(
    const __half* __restrict__ Ah, const __half* __restrict__ BT,
    void* __restrict__ Cv, void* __restrict__ C2v,
    float* __restrict__ fin, float* __restrict__ fou,
    int M, int K, int Nc, const float* __restrict__ bias,
    int lda2, int ldc, int row0, int col0)
{
    __shared__ __align__(16) float sSta[GBM][STA_LD];   // 34816 B; As/Bs aliased inside
    unsigned (*As2)[17] = reinterpret_cast<unsigned(*)[17]>(&sSta[0][0]);
    unsigned (*Bs2)[17] = reinterpret_cast<unsigned(*)[17]>(reinterpret_cast<char*>(&sSta[0][0]) + 8704);
    const int tid  = threadIdx.x;
    const int lane = tid & 31;
    const int wid  = tid >> 5;
    const int wm   = (wid & 3) * 32;
    const int wn   = (wid >> 2) * 32;
    const int grp  = lane >> 2;
    const int tig  = lane & 3;
    const unsigned* BT2 = (const unsigned*)BT;
    const unsigned* A2  = (const unsigned*)Ah;
    const int Kh = K >> 1;

    float c[2][4][4];
#pragma unroll
    for (int mi = 0; mi < 2; mi++)
#pragma unroll
        for (int ni = 0; ni < 4; ni++)
#pragma unroll
            for (int e = 0; e < 4; e++) c[mi][ni][e] = 0.f;

    for (int k0 = 0; k0 < K; k0 += GBK) {
#pragma unroll
        for (int l = 0; l < 8; l++) {
            int linear = tid + l * 256;
            int r = linear >> 4, k2 = linear & 15;
            int gr = row0 + r, gk2 = (k0 >> 1) + k2;
            As2[r][k2] = (gr < M && gk2 < Kh) ? A2[(size_t)gr * lda2 + gk2] : 0u;
        }
#pragma unroll
        for (int p = 0; p < 4; p++) {
            int linear = tid + p * 256;
            int n = linear >> 4, k2 = linear & 15;
            int gc = col0 + n, gk2 = (k0 >> 1) + k2;
            Bs2[n][k2] = (gc < Nc && gk2 < Kh) ? BT2[(size_t)gc * Kh + gk2] : 0u;
        }
        __syncthreads();
#pragma unroll
        for (int ks = 0; ks < 2; ks++) {
            const int kb = ks * 8;
            unsigned a[2][4], b[4][2];
#pragma unroll
            for (int mi = 0; mi < 2; mi++) {
                int r = wm + mi * 16 + grp;
                a[mi][0] = As2[r][kb + tig];
                a[mi][1] = As2[r + 8][kb + tig];
                a[mi][2] = As2[r][kb + tig + 4];
                a[mi][3] = As2[r + 8][kb + tig + 4];
            }
#pragma unroll
            for (int ni = 0; ni < 4; ni++) {
                int cn = wn + ni * 8 + grp;
                b[ni][0] = Bs2[cn][kb + tig];
                b[ni][1] = Bs2[cn][kb + tig + 4];
            }
#pragma unroll
            for (int mi = 0; mi < 2; mi++)
#pragma unroll
                for (int ni = 0; ni < 4; ni++)
                    asm volatile(
                        "mma.sync.aligned.m16n8k16.row.col.f32.f16.f16.f32 "
                        "{%0,%1,%2,%3}, {%4,%5,%6,%7}, {%8,%9}, {%0,%1,%2,%3};"
                        : "+f"(c[mi][ni][0]), "+f"(c[mi][ni][1]),
                          "+f"(c[mi][ni][2]), "+f"(c[mi][ni][3])
                        : "r"(a[mi][0]), "r"(a[mi][1]), "r"(a[mi][2]), "r"(a[mi][3]),
                          "r"(b[ni][0]), "r"(b[ni][1]));
        }
        __syncthreads();
    }
    // ---- stage fragments to smem ----
#pragma unroll
    for (int mi = 0; mi < 2; mi++)
#pragma unroll
        for (int ni = 0; ni < 4; ni++)
#pragma unroll
            for (int h = 0; h < 2; h++) {
                int r  = wm + mi * 16 + grp + h * 8;
                int cn = wn + ni * 8 + tig * 2;
                sSta[r][cn]     = c[mi][ni][h * 2 + 0];
                sSta[r][cn + 1] = c[mi][ni][h * 2 + 1];
            }
    __syncthreads();
    // ---- coalesced readout ----
    const int rl0 = tid >> 4;
    const int c4  = (tid & 15) * 4;
    const int cn  = col0 + c4;
    if (cn < Nc) {
#pragma unroll
        for (int p = 0; p < 8; p++) {
            const int rl = p * 16 + rl0;
            const int r  = row0 + rl;
            if (r >= M) break;
            float4 v = *(const float4*)&sSta[rl][c4];
            if (EPI == 0) {
                uint2 hh = make_uint2(pack_h2(v.x, v.y), pack_h2(v.z, v.w));
                *(uint2*)((__half*)Cv + (size_t)r * ldc + cn) = hh;
            } else {
                v = add4(v, *(const float4*)&bias[cn]);
                if (EPI == 2) {
                    if (cn < 132) {
                        *(float4*)&fou[(size_t)r * 132 + cn] = v;
                    } else {
                        size_t o = (size_t)r * 128 + (cn - 132);
                        *(float4*)&((float*)Cv)[o] = v;                    // fiv
                        *(uint2*)&((__half*)C2v)[o] =
                            make_uint2(pack_h2(v.x, v.y), pack_h2(v.z, v.w)); // fivh
                    }
                } else {   // EPI == 3
                    v.x = (v.x > 0.f) ? v.x : 0.01f * v.x;
                    v.y = (v.y > 0.f) ? v.y : 0.01f * v.y;
                    v.z = (v.z > 0.f) ? v.z : 0.01f * v.z;
                    v.w = (v.w > 0.f) ? v.w : 0.01f * v.w;
                    *(float4*)&((float*)Cv)[(size_t)r * 132 + cn] = v;     // mlp
                    float4 f = *(const float4*)&fou[(size_t)r * 132 + cn];
                    *(float4*)&fin[(size_t)r * 336 + 204 + cn] =
                        mul4(add4(v, f), 0.5f);
                }
            }
        }
    }
}

// ---------------- fused fill (y<256) + GEMM1 (y>=256), per branch ----------------
#define FILL_Y 256
__global__ void __launch_bounds__(256) fill_gemm1_kernel(
    int br,
    const int* __restrict__ idx, const float* __restrict__ val)
{
    if (blockIdx.y < FILL_Y) {
        int* cnt = g_cnt[br];
        const int* rp = g_rowptr[br];
        const int* bo = g_boff[br];
        uint2* edge = g_edge[br];
        const int stride = FILL_Y * 4 * 256;
        for (int e = (blockIdx.y * 4 + blockIdx.x) * 256 + threadIdx.x;
             e < NEDGES; e += stride) {
            int r = idx[e];
            int slot = atomicSub(&cnt[r], 1) - 1;
            int pos = rp[r] + bo[r >> 10] + slot;
            edge[pos] = make_uint2((unsigned)idx[NEDGES + e], __float_as_uint(val[e]));
        }
    } else {
        gemm_body<0>(
            g_xh[br], g_Wc1T, g_Hh[br], nullptr, nullptr, nullptr,
            NNODES, FIN0, F1, nullptr, FIN0 / 2, LD1,
            (blockIdx.y - FILL_Y) * GBM, blockIdx.x * GBN);
    }
}

// GEMM2': (fou | fiv) = Z2 @ [W4|W5] + bc2  (Z2h in g_Hh, stride LD1, K=204)
__global__ void __launch_bounds__(256) gemm2_kernel(int br, float* fiv) {
    gemm_body<2>(
        g_Hh[br], g_Wc2T, fiv, g_fivh[br], nullptr, g_fou[br],
        NNODES, F1, F2, g_bc2, LD1 / 2, 0, blockIdx.y * GBM, blockIdx.x * GBN);
}

__global__ void __launch_bounds__(256) gemm3_kernel(int br, float* mlp, float* fin,
                                                    const float* __restrict__ bm) {
    gemm_body<3>(
        g_fivh[br], g_WmT, mlp, nullptr, fin, g_fou[br],
        NNODES, 128, 132, bm, 64, 132, blockIdx.y * GBM, blockIdx.x * GBN);
}

// ---------------- SpMM1 (warp/node): sigmoid + concat + means (single-pass reduce) ----------------
__device__ __forceinline__ float4 sig4(float4 z) {
    float4 r;
    r.x = 1.f / (1.f + __expf(-z.x));
    r.y = 1.f / (1.f + __expf(-z.y));
    r.z = 1.f / (1.f + __expf(-z.z));
    r.w = 1.f / (1.f + __expf(-z.w));
    return r;
}

__global__ void __launch_bounds__(256) spmm1_kernel(int br,
                                                    float* __restrict__ low,
                                                    float* __restrict__ fin) {
    const int lane = threadIdx.x & 31;
    const int i = blockIdx.x * 8 + (threadIdx.x >> 5);
    if (i >= NNODES) return;
    const int s0 = g_rowptr[br][i]     + g_boff[br][i >> 10];
    const int s1 = g_rowptr[br][i + 1] + g_boff[br][(i + 1) >> 10];
    const uint2* __restrict__ edge = g_edge[br];
    const __half* __restrict__ Hb = g_Hh[br];

    float4 a0 = {0, 0, 0, 0}, a1 = {0, 0, 0, 0};
#pragma unroll 4
    for (int e = s0; e < s1; e++) {
        const uint2 ev = edge[e];                       // uniform: L1 broadcast
        const float v = __uint_as_float(ev.y);
        const uint4* row = (const uint4*)(Hb + (size_t)ev.x * LD1);
        if (lane < 26) {
            uint4 h = row[lane];                        // 8 features
            fma4h(a0, v, make_uint2(h.x, h.y));
            fma4h(a1, v, make_uint2(h.z, h.w));
        }
    }
    const float4* b4 = (const float4*)g_bc1;
    float4 v0 = sig4(add4(a0, b4[2 * lane]));
    float4 v1 = sig4(add4(a1, b4[2 * lane + 1]));
    // categorize: lane l covers features 8l..8l+7 (v0 = 8l..8l+3, v1 = 8l+4..8l+7)
    // sec = 64..131 ; nonthi = 0..131 ; thi = 132..203
    float p_sec = 0.f, p_non = 0.f, p_thi = 0.f;
    if (lane < 16) {
        p_non = sum4(v0) + sum4(v1);
        if (lane >= 8) p_sec = p_non;
    } else if (lane == 16) {
        p_sec = sum4(v0);  p_non = p_sec;  p_thi = sum4(v1);
    } else if (lane < 25) {
        p_thi = sum4(v0) + sum4(v1);
    } else if (lane == 25) {
        p_thi = sum4(v0);
    }
#pragma unroll
    for (int o = 16; o > 0; o >>= 1) {
        p_sec += __shfl_xor_sync(0xFFFFFFFFu, p_sec, o);
        p_non += __shfl_xor_sync(0xFFFFFFFFu, p_non, o);
        p_thi += __shfl_xor_sync(0xFFFFFFFFu, p_thi, o);
    }
    const float mean = p_sec * (1.f / 68.f);
    const float s = 1.f + (p_non + mean * p_thi) * (1.f / 204.f);
    // h_thi scaling (features 132..203)
    float4 w0 = v0, w1 = v1;
    if (lane == 16) w1 = mul4(v1, mean);
    if (lane >= 17) { w0 = mul4(v0, mean); w1 = mul4(v1, mean); }

    float4* lw = (float4*)(low + (size_t)i * F1);
    float4* fn = (float4*)(fin + (size_t)i * 336);
    uint4*  lh = (uint4*)(g_lowh[br] + (size_t)i * LD1);
    if (lane < 26) {
        lh[lane] = make_uint4(pack_h2(w0.x, w0.y), pack_h2(w0.z, w0.w),
                              pack_h2(w1.x, w1.y), pack_h2(w1.z, w1.w));
        lw[2 * lane] = w0;
        fn[2 * lane] = mul4(w0, s);
        if (lane < 25) {
            lw[2 * lane + 1] = w1;
            fn[2 * lane + 1] = mul4(w1, s);
        }
    }
}

// ---------------- SpMM-L (warp/node): Z2 = spmm(lowh) -> fp16, per branch ----------------
__global__ void __launch_bounds__(256) spmmL_kernel(int br) {
    const int lane = threadIdx.x & 31;
    const int i = blockIdx.x * 8 + (threadIdx.x >> 5);
    if (i >= NNODES) return;
    const int s0 = g_rowptr[br][i]     + g_boff[br][i >> 10];
    const int s1 = g_rowptr[br][i + 1] + g_boff[br][(i + 1) >> 10];
    const uint2* __restrict__ edge = g_edge[br];
    const __half* __restrict__ Lb = g_lowh[br];

    float4 a0 = {0, 0, 0, 0}, a1 = {0, 0, 0, 0};
#pragma unroll 4
    for (int e = s0; e < s1; e++) {
        const uint2 ev = edge[e];                       // uniform: L1 broadcast
        const float v = __uint_as_float(ev.y);
        const uint4* row = (const uint4*)(Lb + (size_t)ev.x * LD1);
        if (lane < 26) {
            uint4 h = row[lane];                        // 8 features
            fma4h(a0, v, make_uint2(h.x, h.y));
            fma4h(a1, v, make_uint2(h.z, h.w));
        }
    }
    if (lane < 26) {
        uint4* zrow = (uint4*)(g_Hh[br] + (size_t)i * LD1);
        zrow[lane] = make_uint4(pack_h2(a0.x, a0.y), pack_h2(a0.z, a0.w),
                                pack_h2(a1.x, a1.y), pack_h2(a1.z, a1.w));
    }
}

// ---------------- launch (3-stream prologue fork, 2-stream branch pipelines) ----------------
extern "C" void kernel_launch(void* const* d_in, const int* in_sizes, int n_in,
                              void* d_out, int out_size) {
    const float* x  = (const float*)d_in[0];
    const int*   a1 = (const int*)d_in[1];
    const float* v1 = (const float*)d_in[2];
    const float* y  = (const float*)d_in[3];
    const int*   a2 = (const int*)d_in[4];
    const float* v2 = (const float*)d_in[5];
    const float* W1 = (const float*)d_in[6];
    const float* b1 = (const float*)d_in[7];
    const float* W2 = (const float*)d_in[8];
    const float* b2 = (const float*)d_in[9];
    const float* W3 = (const float*)d_in[10];
    const float* b3 = (const float*)d_in[11];
    const float* W4 = (const float*)d_in[12];
    const float* b4 = (const float*)d_in[13];
    const float* W5 = (const float*)d_in[14];
    const float* b5 = (const float*)d_in[15];
    const float* Wm = (const float*)d_in[16];
    const float* bm = (const float*)d_in[17];
    float* out = (float*)d_out;

    const size_t N = NNODES;
    float* low[2] = { out, out + N * 204 };
    float* fin[2] = { out + 2 * N * 204, out + 2 * N * 204 + N * 336 };
    float* fivx = out + 2 * N * 204 + 2 * N * 336;
    float* mlpx = fivx + N * 128;
    float* fivy = mlpx + N * 132;
    float* mlpy = fivy + N * 128;
    float* fiv[2] = { fivx, fivy };
    float* mlp[2] = { mlpx, mlpy };
    const int* ai[2] = { a1, a2 };
    const float* av[2] = { v1, v2 };

    const int MROWBLKS = (NNODES + GBM - 1) / GBM;   // 391
    const int NB8 = (NNODES + 7) / 8;                // 6250

    // lazily-created streams + events (host resources; identical work each call)
    static cudaStream_t sB = nullptr, sC = nullptr;
    static cudaEvent_t evFork = nullptr, evPack = nullptr, evJoin = nullptr;
    if (!sB) {
        cudaStreamCreateWithFlags(&sB, cudaStreamNonBlocking);
        cudaStreamCreateWithFlags(&sC, cudaStreamNonBlocking);
        cudaEventCreateWithFlags(&evFork, cudaEventDisableTiming);
        cudaEventCreateWithFlags(&evPack, cudaEventDisableTiming);
        cudaEventCreateWithFlags(&evJoin, cudaEventDisableTiming);
    }
    cudaStream_t str[2] = { (cudaStream_t)0, sB };

    // fork immediately: sB and sC start concurrent with stream 0
    cudaEventRecord(evFork, 0);
    cudaStreamWaitEvent(sB, evFork, 0);
    cudaStreamWaitEvent(sC, evFork, 0);

    // sC: weights pack + x/y fp16 convert (needed by fill_gemm1's gemm part)
    pack_conv_kernel<<<256, 256, 0, sC>>>(W1, b1, W2, b2, W3, b3, W4, b4, W5, b5, Wm, x, y);
    cudaEventRecord(evPack, sC);

    // per-branch pipelines; hist+scan run concurrent with pack_conv
    for (int b = 0; b < 2; b++) {
        cudaStream_t s = str[b];
        hist_kernel<<<1024, 256, 0, s>>>(b, ai[b]);
        scan1_kernel<<<SCAN_NB, 1024, 0, s>>>(b);
        cudaStreamWaitEvent(s, evPack, 0);
        fill_gemm1_kernel<<<dim3(4, FILL_Y + MROWBLKS), 256, 0, s>>>(b, ai[b], av[b]);
        spmm1_kernel<<<NB8, 256, 0, s>>>(b, low[b], fin[b]);
        spmmL_kernel<<<NB8, 256, 0, s>>>(b);
        gemm2_kernel<<<dim3(5, MROWBLKS), 256, 0, s>>>(b, fiv[b]);
        gemm3_kernel<<<dim3(3, MROWBLKS), 256, 0, s>>>(b, mlp[b], fin[b], bm);
    }

    // join
    cudaEventRecord(evJoin, sB);
    cudaStreamWaitEvent((cudaStream_t)0, evJoin, 0);
}

// round 17
// speedup vs baseline: 1.0205x; 1.0205x over previous
#include <cuda_runtime.h>
#include <cuda_fp16.h>

#define NNODES 50000
#define NEDGES 800000
#define FIN0   128
#define F1     204      // 64+68+72
#define F2     260      // 132+128
#define LD1    208      // padded halves stride (16B-aligned rows)
#define SCAN_NB  49

// ---------------- device scratch ----------------
__device__ __align__(16) __half g_Hh[2][(size_t)NNODES * LD1];    // H1 (stride LD1), later Z2h (stride LD1)
__device__ __align__(16) __half g_lowh[2][(size_t)NNODES * LD1];  // fp16 low_result
__device__ __align__(16) __half g_xh[2][(size_t)NNODES * FIN0];   // fp16 copies of x,y (GEMM1 A)
__device__ __align__(16) __half g_fivh[2][(size_t)NNODES * 128];  // fp16 h_fiv (GEMM3 A)
__device__ __align__(16) float  g_fou[2][(size_t)NNODES * 132];
__device__ __align__(16) __half g_Wc1T[F1 * FIN0];                // transposed fp16 weights [n][k]
__device__ __align__(16) __half g_Wc2T[F2 * F1];
__device__ __align__(16) __half g_WmT[132 * 128];
__device__ __align__(16) float  g_bc1[256];   // padded, pad stays zero
__device__ __align__(16) float  g_bc2[F2];
__device__ int    g_rowptr[2][NNODES + 2];
__device__ int    g_cnt[2][NNODES];   // always zero between runs: fill's atomicSub restores it
__device__ int    g_boff[2][64];
__device__ __align__(8) uint2  g_edge[2][NEDGES];  // {col, valbits}

__device__ __forceinline__ unsigned pack_h2(float a, float b) {
    __half2 h = __floats2half2_rn(a, b);
    return *(unsigned*)&h;
}

// ---------------- pack weights + convert x/y to fp16 ----------------
__global__ void __launch_bounds__(256) pack_conv_kernel(
    const float* __restrict__ W1, const float* __restrict__ b1,
    const float* __restrict__ W2, const float* __restrict__ b2,
    const float* __restrict__ W3, const float* __restrict__ b3,
    const float* __restrict__ W4, const float* __restrict__ b4,
    const float* __restrict__ W5, const float* __restrict__ b5,
    const float* __restrict__ Wm,
    const float* __restrict__ x, const float* __restrict__ y)
{
    const int t = threadIdx.x;
    const int i = blockIdx.x * 256 + t;
    if (i < F1 * FIN0) {                 // Wc1T[n][k]
        int n = i / FIN0, k = i % FIN0;
        float v = (n < 64) ? W1[k * 64 + n]
                : (n < 132) ? W2[k * 68 + (n - 64)]
                            : W3[k * 72 + (n - 132)];
        g_Wc1T[i] = __float2half(v);
    }
    if (i < F2 * F1) {                   // Wc2T[n][k]
        int n = i / F1, k = i % F1;
        float v = (n < 132) ? W4[k * 132 + n] : W5[k * 128 + (n - 132)];
        g_Wc2T[i] = __float2half(v);
    }
    if (i < 132 * 128) {                 // WmT[n][k]
        int n = i / 128, k = i % 128;
        g_WmT[i] = __float2half(Wm[k * 132 + n]);
    }
    if (i < F1) g_bc1[i] = (i < 64) ? b1[i] : (i < 132) ? b2[i - 64] : b3[i - 132];
    if (i < F2) g_bc2[i] = (i < 132) ? b4[i] : b5[i - 132];
    // convert x,y -> fp16 (vectorized float2 -> half2)
    const int stride = gridDim.x * 256;
    const int nU = NNODES * FIN0 / 2;
    unsigned* dx = (unsigned*)g_xh[0];
    unsigned* dy = (unsigned*)g_xh[1];
    const float2* sx = (const float2*)x;
    const float2* sy = (const float2*)y;
    for (int idx = i; idx < nU; idx += stride) {
        float2 f = sx[idx]; dx[idx] = pack_h2(f.x, f.y);
        float2 g = sy[idx]; dy[idx] = pack_h2(g.x, g.y);
    }
}

// ---------------- per-branch histogram (block 0 zeroes boff) ----------------
__global__ void __launch_bounds__(256) hist_kernel(int br, const int* __restrict__ idx) {
    if (blockIdx.x == 0 && threadIdx.x < 64) g_boff[br][threadIdx.x] = 0;
    int* cnt = g_cnt[br];
    const int stride = gridDim.x * 256;
    for (int e = blockIdx.x * 256 + threadIdx.x; e < NEDGES; e += stride)
        atomicAdd(&cnt[idx[e]], 1);
}

// ---------------- scan (per branch) ----------------
__global__ void __launch_bounds__(1024) scan1_kernel(int br) {
    __shared__ int warp_sums[32];
    __shared__ int sTot;
    const int b = blockIdx.x, t = threadIdx.x;
    const int i = b * 1024 + t;
    const int lane = t & 31, wid = t >> 5;
    int v = (i < NNODES) ? g_cnt[br][i] : 0;
    int s = v;
#pragma unroll
    for (int o = 1; o < 32; o <<= 1) {
        int u = __shfl_up_sync(0xFFFFFFFFu, s, o);
        if (lane >= o) s += u;
    }
    if (lane == 31) warp_sums[wid] = s;
    __syncthreads();
    if (wid == 0) {
        int ws = warp_sums[lane];
#pragma unroll
        for (int o = 1; o < 32; o <<= 1) {
            int u = __shfl_up_sync(0xFFFFFFFFu, ws, o);
            if (lane >= o) ws += u;
        }
        warp_sums[lane] = ws;
    }
    __syncthreads();
    int excl = s - v + (wid > 0 ? warp_sums[wid - 1] : 0);
    if (i <= NNODES) g_rowptr[br][i] = excl;
    if (t == 1023) sTot = excl + v;
    __syncthreads();
    int total = sTot;
    if (t > b && t < SCAN_NB) atomicAdd(&g_boff[br][t], total);
}

// ---------------- standalone CSR fill (low regs, high occ) ----------------
__global__ void __launch_bounds__(256) fill_kernel(int br,
    const int* __restrict__ idx, const float* __restrict__ val)
{
    int* cnt = g_cnt[br];
    const int* rp = g_rowptr[br];
    const int* bo = g_boff[br];
    uint2* edge = g_edge[br];
    const int stride = gridDim.x * 256;
    for (int e = blockIdx.x * 256 + threadIdx.x; e < NEDGES; e += stride) {
        int r = idx[e];
        int slot = atomicSub(&cnt[r], 1) - 1;
        int pos = rp[r] + bo[r >> 10] + slot;
        edge[pos] = make_uint2((unsigned)idx[NEDGES + e], __float_as_uint(val[e]));
    }
}

// ---------------- GEMM helpers ----------------
#define GBM 128
#define GBN 64
#define GBK 32
#define STA_LD 68

__device__ __forceinline__ float4 add4(float4 a, float4 b) {
    return make_float4(a.x + b.x, a.y + b.y, a.z + b.z, a.w + b.w);
}
__device__ __forceinline__ float4 mul4(float4 a, float s) {
    return make_float4(s * a.x, s * a.y, s * a.z, s * a.w);
}
__device__ __forceinline__ void fma4h(float4& a, float v, uint2 h) {
    float2 lo = __half22float2(*(const __half2*)&h.x);
    float2 hi = __half22float2(*(const __half2*)&h.y);
    a.x += v * lo.x; a.y += v * lo.y; a.z += v * hi.x; a.w += v * hi.y;
}
__device__ __forceinline__ float dot4h(float4 a, uint2 h) {
    float2 lo = __half22float2(*(const __half2*)&h.x);
    float2 hi = __half22float2(*(const __half2*)&h.y);
    return a.x * lo.x + a.y * lo.y + a.z * hi.x + a.w * hi.y;
}
__device__ __forceinline__ float sum4(float4 a) { return a.x + a.y + a.z + a.w; }

// ---------------- GEMM body (fp16 A, smem-staged coalesced epilogue) ----------------
// EPI: 0 = fp16 out (gemm1), 2 = split fou/fiv/fivh + bias (gemm2'), 3 = leaky + mlp + fin fuse (gemm3)
template<int EPI>
__device__ __forceinline__ void gemm_body(
    const __half* __restrict__ Ah, const __half* __restrict__ BT,
    void* __restrict__ Cv, void* __restrict__ C2v,
    float* __restrict__ fin, float* __restrict__ fou,
    int M, int K, int Nc, const float* __restrict__ bias,
    int lda2, int ldc, int row0, int col0)
{
    __shared__ __align__(16) float sSta[GBM][STA_LD];
    unsigned (*As2)[17] = reinterpret_cast<unsigned(*)[17]>(&sSta[0][0]);
    unsigned (*Bs2)[17] = reinterpret_cast<unsigned(*)[17]>(reinterpret_cast<char*>(&sSta[0][0]) + 8704);
    const int tid  = threadIdx.x;
    const int lane = tid & 31;
    const int wid  = tid >> 5;
    const int wm   = (wid & 3) * 32;
    const int wn   = (wid >> 2) * 32;
    const int grp  = lane >> 2;
    const int tig  = lane & 3;
    const unsigned* BT2 = (const unsigned*)BT;
    const unsigned* A2  = (const unsigned*)Ah;
    const int Kh = K >> 1;

    float c[2][4][4];
#pragma unroll
    for (int mi = 0; mi < 2; mi++)
#pragma unroll
        for (int ni = 0; ni < 4; ni++)
#pragma unroll
            for (int e = 0; e < 4; e++) c[mi][ni][e] = 0.f;

    for (int k0 = 0; k0 < K; k0 += GBK) {
#pragma unroll
        for (int l = 0; l < 8; l++) {
            int linear = tid + l * 256;
            int r = linear >> 4, k2 = linear & 15;
            int gr = row0 + r, gk2 = (k0 >> 1) + k2;
            As2[r][k2] = (gr < M && gk2 < Kh) ? A2[(size_t)gr * lda2 + gk2] : 0u;
        }
#pragma unroll
        for (int p = 0; p < 4; p++) {
            int linear = tid + p * 256;
            int n = linear >> 4, k2 = linear & 15;
            int gc = col0 + n, gk2 = (k0 >> 1) + k2;
            Bs2[n][k2] = (gc < Nc && gk2 < Kh) ? BT2[(size_t)gc * Kh + gk2] : 0u;
        }
        __syncthreads();
#pragma unroll
        for (int ks = 0; ks < 2; ks++) {
            const int kb = ks * 8;
            unsigned a[2][4], b[4][2];
#pragma unroll
            for (int mi = 0; mi < 2; mi++) {
                int r = wm + mi * 16 + grp;
                a[mi][0] = As2[r][kb + tig];
                a[mi][1] = As2[r + 8][kb + tig];
                a[mi][2] = As2[r][kb + tig + 4];
                a[mi][3] = As2[r + 8][kb + tig + 4];
            }
#pragma unroll
            for (int ni = 0; ni < 4; ni++) {
                int cn = wn + ni * 8 + grp;
                b[ni][0] = Bs2[cn][kb + tig];
                b[ni][1] = Bs2[cn][kb + tig + 4];
            }
#pragma unroll
            for (int mi = 0; mi < 2; mi++)
#pragma unroll
                for (int ni = 0; ni < 4; ni++)
                    asm volatile(
                        "mma.sync.aligned.m16n8k16.row.col.f32.f16.f16.f32 "
                        "{%0,%1,%2,%3}, {%4,%5,%6,%7}, {%8,%9}, {%0,%1,%2,%3};"
                        : "+f"(c[mi][ni][0]), "+f"(c[mi][ni][1]),
                          "+f"(c[mi][ni][2]), "+f"(c[mi][ni][3])
                        : "r"(a[mi][0]), "r"(a[mi][1]), "r"(a[mi][2]), "r"(a[mi][3]),
                          "r"(b[ni][0]), "r"(b[ni][1]));
        }
        __syncthreads();
    }
#pragma unroll
    for (int mi = 0; mi < 2; mi++)
#pragma unroll
        for (int ni = 0; ni < 4; ni++)
#pragma unroll
            for (int h = 0; h < 2; h++) {
                int r  = wm + mi * 16 + grp + h * 8;
                int cn = wn + ni * 8 + tig * 2;
                sSta[r][cn]     = c[mi][ni][h * 2 + 0];
                sSta[r][cn + 1] = c[mi][ni][h * 2 + 1];
            }
    __syncthreads();
    const int rl0 = tid >> 4;
    const int c4  = (tid & 15) * 4;
    const int cn  = col0 + c4;
    if (cn < Nc) {
#pragma unroll
        for (int p = 0; p < 8; p++) {
            const int rl = p * 16 + rl0;
            const int r  = row0 + rl;
            if (r >= M) break;
            float4 v = *(const float4*)&sSta[rl][c4];
            if (EPI == 0) {
                uint2 hh = make_uint2(pack_h2(v.x, v.y), pack_h2(v.z, v.w));
                *(uint2*)((__half*)Cv + (size_t)r * ldc + cn) = hh;
            } else {
                v = add4(v, *(const float4*)&bias[cn]);
                if (EPI == 2) {
                    if (cn < 132) {
                        *(float4*)&fou[(size_t)r * 132 + cn] = v;
                    } else {
                        size_t o = (size_t)r * 128 + (cn - 132);
                        *(float4*)&((float*)Cv)[o] = v;                    // fiv
                        *(uint2*)&((__half*)C2v)[o] =
                            make_uint2(pack_h2(v.x, v.y), pack_h2(v.z, v.w)); // fivh
                    }
                } else {   // EPI == 3
                    v.x = (v.x > 0.f) ? v.x : 0.01f * v.x;
                    v.y = (v.y > 0.f) ? v.y : 0.01f * v.y;
                    v.z = (v.z > 0.f) ? v.z : 0.01f * v.z;
                    v.w = (v.w > 0.f) ? v.w : 0.01f * v.w;
                    *(float4*)&((float*)Cv)[(size_t)r * 132 + cn] = v;     // mlp
                    float4 f = *(const float4*)&fou[(size_t)r * 132 + cn];
                    *(float4*)&fin[(size_t)r * 336 + 204 + cn] =
                        mul4(add4(v, f), 0.5f);
                }
            }
        }
    }
}

// ---------------- standalone GEMM1 (runs on aux stream) ----------------
__global__ void __launch_bounds__(256) gemm1_kernel(int br) {
    gemm_body<0>(
        g_xh[br], g_Wc1T, g_Hh[br], nullptr, nullptr, nullptr,
        NNODES, FIN0, F1, nullptr, FIN0 / 2, LD1,
        blockIdx.y * GBM, blockIdx.x * GBN);
}

// GEMM2': cols 0..255 only (cols 256..259 folded into spmmL)
__global__ void __launch_bounds__(256) gemm2_kernel(int br, float* fiv) {
    gemm_body<2>(
        g_Hh[br], g_Wc2T, fiv, g_fivh[br], nullptr, g_fou[br],
        NNODES, F1, F2, g_bc2, LD1 / 2, 0, blockIdx.y * GBM, blockIdx.x * GBN);
}

__global__ void __launch_bounds__(256) gemm3_kernel(int br, float* mlp, float* fin,
                                                    const float* __restrict__ bm) {
    gemm_body<3>(
        g_fivh[br], g_WmT, mlp, nullptr, fin, g_fou[br],
        NNODES, 128, 132, bm, 64, 132, blockIdx.y * GBM, blockIdx.x * GBN);
}

// ---------------- SpMM1 (warp/node): sigmoid + concat + means (single-pass reduce) ----------------
__device__ __forceinline__ float4 sig4(float4 z) {
    float4 r;
    r.x = 1.f / (1.f + __expf(-z.x));
    r.y = 1.f / (1.f + __expf(-z.y));
    r.z = 1.f / (1.f + __expf(-z.z));
    r.w = 1.f / (1.f + __expf(-z.w));
    return r;
}

__global__ void __launch_bounds__(256) spmm1_kernel(int br,
                                                    float* __restrict__ low,
                                                    float* __restrict__ fin) {
    const int lane = threadIdx.x & 31;
    const int i = blockIdx.x * 8 + (threadIdx.x >> 5);
    if (i >= NNODES) return;
    const int s0 = g_rowptr[br][i]     + g_boff[br][i >> 10];
    const int s1 = g_rowptr[br][i + 1] + g_boff[br][(i + 1) >> 10];
    const uint2* __restrict__ edge = g_edge[br];
    const __half* __restrict__ Hb = g_Hh[br];

    float4 a0 = {0, 0, 0, 0}, a1 = {0, 0, 0, 0};
#pragma unroll 4
    for (int e = s0; e < s1; e++) {
        const uint2 ev = edge[e];
        const float v = __uint_as_float(ev.y);
        const uint4* row = (const uint4*)(Hb + (size_t)ev.x * LD1);
        if (lane < 26) {
            uint4 h = row[lane];
            fma4h(a0, v, make_uint2(h.x, h.y));
            fma4h(a1, v, make_uint2(h.z, h.w));
        }
    }
    const float4* b4 = (const float4*)g_bc1;
    float4 v0 = sig4(add4(a0, b4[2 * lane]));
    float4 v1 = sig4(add4(a1, b4[2 * lane + 1]));
    float p_sec = 0.f, p_non = 0.f, p_thi = 0.f;
    if (lane < 16) {
        p_non = sum4(v0) + sum4(v1);
        if (lane >= 8) p_sec = p_non;
    } else if (lane == 16) {
        p_sec = sum4(v0);  p_non = p_sec;  p_thi = sum4(v1);
    } else if (lane < 25) {
        p_thi = sum4(v0) + sum4(v1);
    } else if (lane == 25) {
        p_thi = sum4(v0);
    }
#pragma unroll
    for (int o = 16; o > 0; o >>= 1) {
        p_sec += __shfl_xor_sync(0xFFFFFFFFu, p_sec, o);
        p_non += __shfl_xor_sync(0xFFFFFFFFu, p_non, o);
        p_thi += __shfl_xor_sync(0xFFFFFFFFu, p_thi, o);
    }
    const float mean = p_sec * (1.f / 68.f);
    const float s = 1.f + (p_non + mean * p_thi) * (1.f / 204.f);
    float4 w0 = v0, w1 = v1;
    if (lane == 16) w1 = mul4(v1, mean);
    if (lane >= 17) { w0 = mul4(v0, mean); w1 = mul4(v1, mean); }

    float4* lw = (float4*)(low + (size_t)i * F1);
    float4* fn = (float4*)(fin + (size_t)i * 336);
    uint4*  lh = (uint4*)(g_lowh[br] + (size_t)i * LD1);
    if (lane < 26) {
        lh[lane] = make_uint4(pack_h2(w0.x, w0.y), pack_h2(w0.z, w0.w),
                              pack_h2(w1.x, w1.y), pack_h2(w1.z, w1.w));
        lw[2 * lane] = w0;
        fn[2 * lane] = mul4(w0, s);
        if (lane < 25) {
            lw[2 * lane + 1] = w1;
            fn[2 * lane + 1] = mul4(w1, s);
        }
    }
}

// ---------------- SpMM-L: Z2 = spmm(lowh) -> fp16, plus fiv cols 124..127 (W cols 256..259) ----------------
__global__ void __launch_bounds__(256) spmmL_kernel(int br, float* __restrict__ fiv) {
    const int lane = threadIdx.x & 31;
    const int i = blockIdx.x * 8 + (threadIdx.x >> 5);
    if (i >= NNODES) return;
    const int s0 = g_rowptr[br][i]     + g_boff[br][i >> 10];
    const int s1 = g_rowptr[br][i + 1] + g_boff[br][(i + 1) >> 10];
    const uint2* __restrict__ edge = g_edge[br];
    const __half* __restrict__ Lb = g_lowh[br];

    float4 a0 = {0, 0, 0, 0}, a1 = {0, 0, 0, 0};
#pragma unroll 4
    for (int e = s0; e < s1; e++) {
        const uint2 ev = edge[e];
        const float v = __uint_as_float(ev.y);
        const uint4* row = (const uint4*)(Lb + (size_t)ev.x * LD1);
        if (lane < 26) {
            uint4 h = row[lane];
            fma4h(a0, v, make_uint2(h.x, h.y));
            fma4h(a1, v, make_uint2(h.z, h.w));
        }
    }
    if (lane < 26) {
        uint4* zrow = (uint4*)(g_Hh[br] + (size_t)i * LD1);
        zrow[lane] = make_uint4(pack_h2(a0.x, a0.y), pack_h2(a0.z, a0.w),
                                pack_h2(a1.x, a1.y), pack_h2(a1.z, a1.w));
    }
    // fiv cols 124..127 = dot(Z2, Wc2T rows 256..259) + bc2[256..259]
    const unsigned* W = (const unsigned*)g_Wc2T;   // row stride F1/2 = 102 uints
    float d0 = 0.f, d1 = 0.f, d2 = 0.f, d3 = 0.f;
    if (lane < 26) {
#pragma unroll
        for (int j = 0; j < 4; j++) {
            const unsigned* wr = W + (size_t)(256 + j) * 102 + 4 * lane;
            uint2 w0 = *(const uint2*)wr;                 // features 8l..8l+3
            float dj = dot4h(a0, w0);
            if (lane < 25) {
                uint2 w1 = *(const uint2*)(wr + 2);       // features 8l+4..8l+7
                dj += dot4h(a1, w1);
            }
            if (j == 0) d0 = dj; else if (j == 1) d1 = dj;
            else if (j == 2) d2 = dj; else d3 = dj;
        }
    }
#pragma unroll
    for (int o = 16; o > 0; o >>= 1) {
        d0 += __shfl_xor_sync(0xFFFFFFFFu, d0, o);
        d1 += __shfl_xor_sync(0xFFFFFFFFu, d1, o);
        d2 += __shfl_xor_sync(0xFFFFFFFFu, d2, o);
        d3 += __shfl_xor_sync(0xFFFFFFFFu, d3, o);
    }
    if (lane == 0) {
        const float4 bb = *(const float4*)&g_bc2[256];
        float4 z = make_float4(d0 + bb.x, d1 + bb.y, d2 + bb.z, d3 + bb.w);
        size_t o = (size_t)i * 128 + 124;
        *(float4*)&fiv[o] = z;
        *(uint2*)&g_fivh[br][o] = make_uint2(pack_h2(z.x, z.y), pack_h2(z.z, z.w));
    }
}

// ---------------- launch (3 streams: 2 branch pipelines + gemm1/pack aux) ----------------
extern "C" void kernel_launch(void* const* d_in, const int* in_sizes, int n_in,
                              void* d_out, int out_size) {
    const float* x  = (const float*)d_in[0];
    const int*   a1 = (const int*)d_in[1];
    const float* v1 = (const float*)d_in[2];
    const float* y  = (const float*)d_in[3];
    const int*   a2 = (const int*)d_in[4];
    const float* v2 = (const float*)d_in[5];
    const float* W1 = (const float*)d_in[6];
    const float* b1 = (const float*)d_in[7];
    const float* W2 = (const float*)d_in[8];
    const float* b2 = (const float*)d_in[9];
    const float* W3 = (const float*)d_in[10];
    const float* b3 = (const float*)d_in[11];
    const float* W4 = (const float*)d_in[12];
    const float* b4 = (const float*)d_in[13];
    const float* W5 = (const float*)d_in[14];
    const float* b5 = (const float*)d_in[15];
    const float* Wm = (const float*)d_in[16];
    const float* bm = (const float*)d_in[17];
    float* out = (float*)d_out;

    const size_t N = NNODES;
    float* low[2] = { out, out + N * 204 };
    float* fin[2] = { out + 2 * N * 204, out + 2 * N * 204 + N * 336 };
    float* fivx = out + 2 * N * 204 + 2 * N * 336;
    float* mlpx = fivx + N * 128;
    float* fivy = mlpx + N * 132;
    float* mlpy = fivy + N * 128;
    float* fiv[2] = { fivx, fivy };
    float* mlp[2] = { mlpx, mlpy };
    const int* ai[2] = { a1, a2 };
    const float* av[2] = { v1, v2 };

    const int MROWBLKS = (NNODES + GBM - 1) / GBM;   // 391
    const int NB8 = (NNODES + 7) / 8;                // 6250

    static cudaStream_t sB = nullptr, sC = nullptr;
    static cudaEvent_t evFork = nullptr, evJoin = nullptr;
    static cudaEvent_t evG1[2] = { nullptr, nullptr };
    if (!sB) {
        cudaStreamCreateWithFlags(&sB, cudaStreamNonBlocking);
        cudaStreamCreateWithFlags(&sC, cudaStreamNonBlocking);
        cudaEventCreateWithFlags(&evFork, cudaEventDisableTiming);
        cudaEventCreateWithFlags(&evJoin, cudaEventDisableTiming);
        cudaEventCreateWithFlags(&evG1[0], cudaEventDisableTiming);
        cudaEventCreateWithFlags(&evG1[1], cudaEventDisableTiming);
    }
    cudaStream_t str[2] = { (cudaStream_t)0, sB };

    // fork
    cudaEventRecord(evFork, 0);
    cudaStreamWaitEvent(sB, evFork, 0);
    cudaStreamWaitEvent(sC, evFork, 0);

    // aux stream: pack/convert then both gemm1s
    pack_conv_kernel<<<256, 256, 0, sC>>>(W1, b1, W2, b2, W3, b3, W4, b4, W5, b5, Wm, x, y);
    gemm1_kernel<<<dim3(4, MROWBLKS), 256, 0, sC>>>(0);
    cudaEventRecord(evG1[0], sC);
    gemm1_kernel<<<dim3(4, MROWBLKS), 256, 0, sC>>>(1);
    cudaEventRecord(evG1[1], sC);

    // branch pipelines
    for (int b = 0; b < 2; b++) {
        cudaStream_t s = str[b];
        hist_kernel<<<1024, 256, 0, s>>>(b, ai[b]);
        scan1_kernel<<<SCAN_NB, 1024, 0, s>>>(b);
        fill_kernel<<<1024, 256, 0, s>>>(b, ai[b], av[b]);
        cudaStreamWaitEvent(s, evG1[b], 0);
        spmm1_kernel<<<NB8, 256, 0, s>>>(b, low[b], fin[b]);
        spmmL_kernel<<<NB8, 256, 0, s>>>(b, fiv[b]);
        gemm2_kernel<<<dim3(4, MROWBLKS), 256, 0, s>>>(b, fiv[b]);
        gemm3_kernel<<<dim3(3, MROWBLKS), 256, 0, s>>>(b, mlp[b], fin[b], bm);
    }

    // join
    cudaEventRecord(evJoin, sB);
    cudaStreamWaitEvent((cudaStream_t)0, evJoin, 0);
}